// round 1
// baseline (speedup 1.0000x reference)
#include <cuda_runtime.h>
#include <cuda_bf16.h>
#include <math.h>

#define FULL 0xffffffffu

static const int NMAX = 50000;
static const long long EMAX = 1600000;

// ---------------- scratch (static __device__ — no allocation) ----------------
__device__ __align__(16) float g_h1[NMAX * 128];    // layer1 pre-agg features
__device__ __align__(16) float g_l1[NMAX * 128];    // layer1 output (post relu)
__device__ __align__(16) float g_h2[NMAX * 64];     // layer2 pre-agg features
__device__ __align__(16) float g_as1[NMAX * 4];
__device__ __align__(16) float g_ad1[NMAX * 4];
__device__ float g_as2[NMAX];
__device__ float g_ad2[NMAX];
__device__ int   g_cnt[NMAX];
__device__ int   g_offs[NMAX + 1];
__device__ int   g_cur[NMAX];
__device__ int   g_srcs[EMAX + NMAX];
__device__ int   g_is64;

// ---------------- edge dtype detection ----------------
__global__ void detect_k(const void* ei, int n) {
    if (threadIdx.x == 0) {
        const long long* p = (const long long*)ei;
        int ok = 1;
        for (int i = 0; i < 64; i++) {
            long long v = p[i];
            if (v < 0 || v >= (long long)n) { ok = 0; break; }
        }
        g_is64 = ok;
    }
}

__device__ __forceinline__ int edge_src(const void* ei, long long E, long long i) {
    return g_is64 ? (int)((const long long*)ei)[i] : ((const int*)ei)[i];
}
__device__ __forceinline__ int edge_dst(const void* ei, long long E, long long i) {
    return g_is64 ? (int)((const long long*)ei)[E + i] : ((const int*)ei)[E + i];
}

// ---------------- GEMM: C[n,NC] = A[n,128] @ W[128,NC] ----------------
template <int NC>
__global__ void gemm_k(const float* __restrict__ A, const float* __restrict__ W,
                       float* __restrict__ C, int n) {
    const int BM = 64, BK = 16, TM = 8, TN = 4;
    const int TX = NC / TN;              // 32 (NC=128) or 16 (NC=64)
    __shared__ float AsT[BK][BM + 1];
    __shared__ float Ws[BK][NC];

    int tid  = threadIdx.x;              // TX * 8 threads
    int tcol = tid % TX;
    int trow = tid / TX;
    int row0 = blockIdx.x * BM;

    float acc[TM][TN];
#pragma unroll
    for (int i = 0; i < TM; i++)
#pragma unroll
        for (int j = 0; j < TN; j++) acc[i][j] = 0.f;

    for (int kc = 0; kc < 128; kc += BK) {
        for (int idx = tid; idx < BM * BK; idx += blockDim.x) {
            int kk = idx % BK, r = idx / BK;
            int gr = row0 + r;
            AsT[kk][r] = (gr < n) ? A[(size_t)gr * 128 + kc + kk] : 0.f;
        }
        for (int idx = tid; idx < BK * NC; idx += blockDim.x) {
            int cc = idx % NC, kk = idx / NC;
            Ws[kk][cc] = W[(kc + kk) * NC + cc];
        }
        __syncthreads();
#pragma unroll
        for (int kk = 0; kk < BK; kk++) {
            float a[TM];
#pragma unroll
            for (int i = 0; i < TM; i++) a[i] = AsT[kk][trow * TM + i];
            float4 bv = *reinterpret_cast<const float4*>(&Ws[kk][tcol * TN]);
            float b[TN] = {bv.x, bv.y, bv.z, bv.w};
#pragma unroll
            for (int i = 0; i < TM; i++)
#pragma unroll
                for (int j = 0; j < TN; j++) acc[i][j] += a[i] * b[j];
        }
        __syncthreads();
    }
#pragma unroll
    for (int i = 0; i < TM; i++) {
        int gr = row0 + trow * TM + i;
        if (gr < n) {
#pragma unroll
            for (int j = 0; j < TN; j++)
                C[(size_t)gr * NC + tcol * TN + j] = acc[i][j];
        }
    }
}

// ---------------- alpha projections ----------------
__global__ void alpha1_k(const float* __restrict__ h, const float* __restrict__ a_src,
                         const float* __restrict__ a_dst, float* __restrict__ asrc,
                         float* __restrict__ adst, int n) {
    int warp = (blockIdx.x * blockDim.x + threadIdx.x) >> 5;
    int lane = threadIdx.x & 31;
    int nw = (gridDim.x * blockDim.x) >> 5;
    for (int v = warp; v < n; v += nw) {
#pragma unroll
        for (int hd = 0; hd < 4; hd++) {
            float x  = h[(size_t)v * 128 + hd * 32 + lane];
            float s1 = x * a_src[hd * 32 + lane];
            float s2 = x * a_dst[hd * 32 + lane];
#pragma unroll
            for (int o = 16; o; o >>= 1) {
                s1 += __shfl_xor_sync(FULL, s1, o);
                s2 += __shfl_xor_sync(FULL, s2, o);
            }
            if (lane == 0) {
                asrc[v * 4 + hd] = s1;
                adst[v * 4 + hd] = s2;
            }
        }
    }
}

__global__ void alpha2_k(const float* __restrict__ h, const float* __restrict__ a_src,
                         const float* __restrict__ a_dst, float* __restrict__ asrc,
                         float* __restrict__ adst, int n) {
    int warp = (blockIdx.x * blockDim.x + threadIdx.x) >> 5;
    int lane = threadIdx.x & 31;
    int nw = (gridDim.x * blockDim.x) >> 5;
    for (int v = warp; v < n; v += nw) {
        float x0 = h[(size_t)v * 64 + lane];
        float x1 = h[(size_t)v * 64 + 32 + lane];
        float s1 = x0 * a_src[lane] + x1 * a_src[32 + lane];
        float s2 = x0 * a_dst[lane] + x1 * a_dst[32 + lane];
#pragma unroll
        for (int o = 16; o; o >>= 1) {
            s1 += __shfl_xor_sync(FULL, s1, o);
            s2 += __shfl_xor_sync(FULL, s2, o);
        }
        if (lane == 0) { asrc[v] = s1; adst[v] = s2; }
    }
}

// ---------------- CSR build ----------------
__global__ void zero_k(int* __restrict__ cnt, int n) {
    for (int i = blockIdx.x * blockDim.x + threadIdx.x; i < n; i += gridDim.x * blockDim.x)
        cnt[i] = 0;
}

__global__ void hist_k(const void* ei, long long E, int n, int* __restrict__ cnt) {
    long long total = E + n;
    for (long long i = (long long)blockIdx.x * blockDim.x + threadIdx.x; i < total;
         i += (long long)gridDim.x * blockDim.x) {
        int d = (i < E) ? edge_dst(ei, E, i) : (int)(i - E);
        atomicAdd(&cnt[d], 1);
    }
}

__global__ void scan_k(const int* __restrict__ cnt, int* __restrict__ offs,
                       int* __restrict__ cur, int n) {
    __shared__ int sm[1024];
    int tid = threadIdx.x;
    int chunk = (n + 1023) / 1024;
    int start = tid * chunk;
    int end = min(start + chunk, n);
    int s = 0;
    for (int i = start; i < end; i++) s += cnt[i];
    sm[tid] = s;
    __syncthreads();
    for (int o = 1; o < 1024; o <<= 1) {
        int v = (tid >= o) ? sm[tid - o] : 0;
        __syncthreads();
        sm[tid] += v;
        __syncthreads();
    }
    int run = (tid == 0) ? 0 : sm[tid - 1];
    for (int i = start; i < end; i++) {
        offs[i] = run;
        cur[i] = run;
        run += cnt[i];
    }
    if (tid == 1023) offs[n] = sm[1023];
}

__global__ void scat_k(const void* ei, long long E, int n, int* __restrict__ cur,
                       int* __restrict__ srcs) {
    long long total = E + n;
    for (long long i = (long long)blockIdx.x * blockDim.x + threadIdx.x; i < total;
         i += (long long)gridDim.x * blockDim.x) {
        int s, d;
        if (i < E) { s = edge_src(ei, E, i); d = edge_dst(ei, E, i); }
        else { s = d = (int)(i - E); }
        int pos = atomicAdd(&cur[d], 1);
        srcs[pos] = s;
    }
}

// ---------------- layer1 aggregation: one warp per dst node ----------------
__global__ void agg1_k(const float* __restrict__ h, const float* __restrict__ asrc,
                       const float* __restrict__ adst, const int* __restrict__ offs,
                       const int* __restrict__ srcs, const float* __restrict__ b1,
                       float* __restrict__ out, int n) {
    int warp = (blockIdx.x * blockDim.x + threadIdx.x) >> 5;
    int lane = threadIdx.x & 31;
    int nw = (gridDim.x * blockDim.x) >> 5;
    for (int v = warp; v < n; v += nw) {
        int s0 = offs[v], s1e = offs[v + 1];
        float4 ad = *reinterpret_cast<const float4*>(asrc == asrc ? &adst[v * 4] : &adst[v * 4]);
        // pass 1: per-head max
        float m0 = -1e30f, m1 = -1e30f, m2 = -1e30f, m3 = -1e30f;
        for (int i = s0 + lane; i < s1e; i += 32) {
            int src = srcs[i];
            float4 as = *reinterpret_cast<const float4*>(&asrc[src * 4]);
            float e0 = as.x + ad.x; e0 = e0 > 0.f ? e0 : 0.2f * e0;
            float e1 = as.y + ad.y; e1 = e1 > 0.f ? e1 : 0.2f * e1;
            float e2 = as.z + ad.z; e2 = e2 > 0.f ? e2 : 0.2f * e2;
            float e3 = as.w + ad.w; e3 = e3 > 0.f ? e3 : 0.2f * e3;
            m0 = fmaxf(m0, e0); m1 = fmaxf(m1, e1);
            m2 = fmaxf(m2, e2); m3 = fmaxf(m3, e3);
        }
#pragma unroll
        for (int o = 16; o; o >>= 1) {
            m0 = fmaxf(m0, __shfl_xor_sync(FULL, m0, o));
            m1 = fmaxf(m1, __shfl_xor_sync(FULL, m1, o));
            m2 = fmaxf(m2, __shfl_xor_sync(FULL, m2, o));
            m3 = fmaxf(m3, __shfl_xor_sync(FULL, m3, o));
        }
        // pass 2: exp + weighted accumulation (lane owns one channel per head)
        float den0 = 0.f, den1 = 0.f, den2 = 0.f, den3 = 0.f;
        float a0 = 0.f, a1 = 0.f, a2 = 0.f, a3 = 0.f;
        for (int base = s0; base < s1e; base += 32) {
            int i = base + lane;
            float p0 = 0.f, p1 = 0.f, p2 = 0.f, p3 = 0.f;
            int src = 0;
            if (i < s1e) {
                src = srcs[i];
                float4 as = *reinterpret_cast<const float4*>(&asrc[src * 4]);
                float e;
                e = as.x + ad.x; e = e > 0.f ? e : 0.2f * e; p0 = __expf(e - m0);
                e = as.y + ad.y; e = e > 0.f ? e : 0.2f * e; p1 = __expf(e - m1);
                e = as.z + ad.z; e = e > 0.f ? e : 0.2f * e; p2 = __expf(e - m2);
                e = as.w + ad.w; e = e > 0.f ? e : 0.2f * e; p3 = __expf(e - m3);
            }
            int cnt = min(32, s1e - base);
            for (int j = 0; j < cnt; j++) {
                int   sj = __shfl_sync(FULL, src, j);
                float q0 = __shfl_sync(FULL, p0, j);
                float q1 = __shfl_sync(FULL, p1, j);
                float q2 = __shfl_sync(FULL, p2, j);
                float q3 = __shfl_sync(FULL, p3, j);
                den0 += q0; den1 += q1; den2 += q2; den3 += q3;
                const float* hp = h + (size_t)sj * 128;
                a0 += q0 * hp[lane];
                a1 += q1 * hp[32 + lane];
                a2 += q2 * hp[64 + lane];
                a3 += q3 * hp[96 + lane];
            }
        }
        float o0 = a0 / (den0 + 1e-16f) + b1[lane];
        float o1 = a1 / (den1 + 1e-16f) + b1[32 + lane];
        float o2 = a2 / (den2 + 1e-16f) + b1[64 + lane];
        float o3 = a3 / (den3 + 1e-16f) + b1[96 + lane];
        float* op = out + (size_t)v * 128;
        op[lane]      = fmaxf(o0, 0.f);
        op[32 + lane] = fmaxf(o1, 0.f);
        op[64 + lane] = fmaxf(o2, 0.f);
        op[96 + lane] = fmaxf(o3, 0.f);
    }
}

// ---------------- layer2 aggregation (1 head, 64 ch) ----------------
__global__ void agg2_k(const float* __restrict__ h, const float* __restrict__ asrc,
                       const float* __restrict__ adst, const int* __restrict__ offs,
                       const int* __restrict__ srcs, const float* __restrict__ b2,
                       float* __restrict__ out, int n) {
    int warp = (blockIdx.x * blockDim.x + threadIdx.x) >> 5;
    int lane = threadIdx.x & 31;
    int nw = (gridDim.x * blockDim.x) >> 5;
    for (int v = warp; v < n; v += nw) {
        int s0 = offs[v], s1e = offs[v + 1];
        float ad = adst[v];
        float m = -1e30f;
        for (int i = s0 + lane; i < s1e; i += 32) {
            int src = srcs[i];
            float e = asrc[src] + ad;
            e = e > 0.f ? e : 0.2f * e;
            m = fmaxf(m, e);
        }
#pragma unroll
        for (int o = 16; o; o >>= 1) m = fmaxf(m, __shfl_xor_sync(FULL, m, o));
        float den = 0.f, a0 = 0.f, a1 = 0.f;
        for (int base = s0; base < s1e; base += 32) {
            int i = base + lane;
            float p = 0.f;
            int src = 0;
            if (i < s1e) {
                src = srcs[i];
                float e = asrc[src] + ad;
                e = e > 0.f ? e : 0.2f * e;
                p = __expf(e - m);
            }
            int cnt = min(32, s1e - base);
            for (int j = 0; j < cnt; j++) {
                int   sj = __shfl_sync(FULL, src, j);
                float q  = __shfl_sync(FULL, p, j);
                den += q;
                const float* hp = h + (size_t)sj * 64;
                a0 += q * hp[lane];
                a1 += q * hp[32 + lane];
            }
        }
        out[(size_t)v * 64 + lane]      = a0 / (den + 1e-16f) + b2[lane];
        out[(size_t)v * 64 + 32 + lane] = a1 / (den + 1e-16f) + b2[32 + lane];
    }
}

// ---------------- launch ----------------
extern "C" void kernel_launch(void* const* d_in, const int* in_sizes, int n_in,
                              void* d_out, int out_size) {
    const float* x   = (const float*)d_in[0];
    const void*  ei  = d_in[1];
    const float* W1  = (const float*)d_in[2];
    const float* as1 = (const float*)d_in[3];
    const float* ad1 = (const float*)d_in[4];
    const float* b1  = (const float*)d_in[5];
    const float* W2  = (const float*)d_in[6];
    const float* as2 = (const float*)d_in[7];
    const float* ad2 = (const float*)d_in[8];
    const float* b2  = (const float*)d_in[9];
    float* out = (float*)d_out;

    int n = in_sizes[0] / 128;           // 50000
    long long E = in_sizes[1] / 2;       // 1600000 (element count same for i32/i64)

    float *p_h1, *p_l1, *p_h2, *p_as1, *p_ad1, *p_as2, *p_ad2;
    int *p_cnt, *p_offs, *p_cur, *p_srcs;
    cudaGetSymbolAddress((void**)&p_h1, g_h1);
    cudaGetSymbolAddress((void**)&p_l1, g_l1);
    cudaGetSymbolAddress((void**)&p_h2, g_h2);
    cudaGetSymbolAddress((void**)&p_as1, g_as1);
    cudaGetSymbolAddress((void**)&p_ad1, g_ad1);
    cudaGetSymbolAddress((void**)&p_as2, g_as2);
    cudaGetSymbolAddress((void**)&p_ad2, g_ad2);
    cudaGetSymbolAddress((void**)&p_cnt, g_cnt);
    cudaGetSymbolAddress((void**)&p_offs, g_offs);
    cudaGetSymbolAddress((void**)&p_cur, g_cur);
    cudaGetSymbolAddress((void**)&p_srcs, g_srcs);

    int gemm_blocks = (n + 63) / 64;
    int warp_blocks = (n * 32 + 255) / 256;

    detect_k<<<1, 32>>>(ei, n);
    gemm_k<128><<<gemm_blocks, 256>>>(x, W1, p_h1, n);
    alpha1_k<<<warp_blocks, 256>>>(p_h1, as1, ad1, p_as1, p_ad1, n);
    zero_k<<<200, 256>>>(p_cnt, n);
    hist_k<<<2048, 256>>>(ei, E, n, p_cnt);
    scan_k<<<1, 1024>>>(p_cnt, p_offs, p_cur, n);
    scat_k<<<2048, 256>>>(ei, E, n, p_cur, p_srcs);
    agg1_k<<<warp_blocks, 256>>>(p_h1, p_as1, p_ad1, p_offs, p_srcs, b1, p_l1, n);
    gemm_k<64><<<gemm_blocks, 128>>>(p_l1, W2, p_h2, n);
    alpha2_k<<<warp_blocks, 256>>>(p_h2, as2, ad2, p_as2, p_ad2, n);
    agg2_k<<<warp_blocks, 256>>>(p_h2, p_as2, p_ad2, p_offs, p_srcs, b2, out, n);
}